// round 9
// baseline (speedup 1.0000x reference)
#include <cuda_runtime.h>
#include <cuda_fp16.h>

#define N_NODES 50000
#define N_EDGES 800000
#define DH 64
#define NG 64
#define NCHUNK ((N_NODES + 255) / 256)   // 196
#define NBAR 12

// ---------------- device scratch ----------------
__device__ float  g_dinv[N_NODES];
__device__ int    g_degi[N_NODES];
__device__ int    g_off[N_NODES + 1];
__device__ int    g_cur[N_NODES];
__device__ int    g_bsum[NCHUNK];
__device__ int    g_bpre[NCHUNK];
__device__ int2   g_edge[N_EDGES];
__device__ uint2  g_t16[N_NODES * 16];      // t in fp16 (4 halfs per uint2)
__device__ float4 g_h[N_NODES * 16];        // layer output (fp32)
__device__ int    g_start[NG + 1];

// barrier state (reset by last block each run)
__device__ unsigned int g_bar[NBAR];
__device__ unsigned int g_done;

__device__ __forceinline__ float4 f4add(float4 a, float4 b) {
    return make_float4(a.x + b.x, a.y + b.y, a.z + b.z, a.w + b.w);
}

// packed f32x2 helpers (Blackwell dual-FP32 pipe; PTX-only)
__device__ __forceinline__ unsigned long long pk2(float a, float b) {
    unsigned long long r;
    asm("mov.b64 %0, {%1, %2};" : "=l"(r) : "f"(a), "f"(b));
    return r;
}
__device__ __forceinline__ void fma2(unsigned long long& d,
                                     unsigned long long a, unsigned long long b) {
    asm("fma.rn.f32x2 %0, %1, %2, %0;" : "+l"(d) : "l"(a), "l"(b));
}
__device__ __forceinline__ float2 upk2(unsigned long long v) {
    float2 f;
    asm("mov.b64 {%0, %1}, %2;" : "=f"(f.x), "=f"(f.y) : "l"(v));
    return f;
}
__device__ __forceinline__ void upk_h4(uint2 u, float2& a, float2& b) {
    a = __half22float2(*(const __half2*)&u.x);
    b = __half22float2(*(const __half2*)&u.y);
}

// grid-wide barrier: per-barrier counter, canonical threadfence pattern
__device__ __forceinline__ void gbar(int k) {
    __syncthreads();
    if (threadIdx.x == 0) {
        __threadfence();
        atomicAdd(&g_bar[k], 1u);
        while (*((volatile unsigned int*)&g_bar[k]) < gridDim.x) {}
        __threadfence();
    }
    __syncthreads();
}

// ---------------- the whole GCN in one persistent kernel ------------------
__global__ void __launch_bounds__(256)
fused_gcn(const float* __restrict__ x,
          const int* __restrict__ ei,
          const int* __restrict__ batch,
          const float* __restrict__ W0, const float* __restrict__ B0,
          const float* __restrict__ W1, const float* __restrict__ B1,
          const float* __restrict__ W2, const float* __restrict__ B2,
          float* __restrict__ out) {
    __shared__ float4 sh[DH * 16];          // 16 KB, aliased per phase
    int* si = (int*)sh;

    const int tid  = threadIdx.x;
    const int bid  = blockIdx.x;
    const int nblk = gridDim.x;
    const int nthr = nblk * 256;
    const int gt   = bid * 256 + tid;

    // ---- P0: clear degrees ----
    for (int i = gt; i < N_NODES; i += nthr) g_degi[i] = 0;
    gbar(0);

    // ---- P1: in-degrees ----
    const int* col = ei + N_EDGES;
    for (int e = gt; e < N_EDGES; e += nthr) {
        int c = col[e];
        if ((unsigned)c < (unsigned)N_NODES) atomicAdd(&g_degi[c], 1);
    }
    gbar(1);

    // ---- P2: per-chunk (256) scan of degrees + dinv ----
    for (int c = bid; c < NCHUNK; c += nblk) {
        int i = c * 256 + tid;
        int v = (i < N_NODES) ? g_degi[i] : 0;
        if (i < N_NODES) g_dinv[i] = rsqrtf((float)v + 1.0f);  // +1 self loop
        si[tid] = v;
        __syncthreads();
#pragma unroll
        for (int d = 1; d < 256; d <<= 1) {
            int u = (tid >= d) ? si[tid - d] : 0;
            __syncthreads();
            si[tid] += u;
            __syncthreads();
        }
        if (i < N_NODES) g_off[i] = si[tid] - v;   // local exclusive
        if (tid == 255) g_bsum[c] = si[255];
        __syncthreads();
    }
    gbar(2);

    // ---- P3: block 0 scans the 196 chunk sums ----
    if (bid == 0) {
        int v = (tid < NCHUNK) ? g_bsum[tid] : 0;
        si[tid] = v;
        __syncthreads();
#pragma unroll
        for (int d = 1; d < 256; d <<= 1) {
            int u = (tid >= d) ? si[tid - d] : 0;
            __syncthreads();
            si[tid] += u;
            __syncthreads();
        }
        if (tid < NCHUNK) g_bpre[tid] = si[tid] - v;
        if (tid == 255) g_off[N_NODES] = si[255];
        __syncthreads();
    }
    gbar(3);

    // ---- P4: global offsets + cursor + graph bounds ----
    for (int i = gt; i < N_NODES; i += nthr) {
        int off = g_off[i] + g_bpre[i >> 8];
        g_off[i] = off;
        g_cur[i] = off;
        int b  = batch[i];
        int bp = (i == 0) ? -1 : batch[i - 1];
        if (b < 0) b = 0;
        if (b >= NG) b = NG - 1;
        if (bp < -1) bp = -1;
        if (bp >= NG) bp = NG - 1;
        for (int g = bp + 1; g <= b; g++) g_start[g] = i;
        if (i == N_NODES - 1)
            for (int g = b + 1; g <= NG; g++) g_start[g] = N_NODES;
    }
    gbar(4);

    // ---- P5: scatter edges into CSR (by destination) ----
    for (int e = gt; e < N_EDGES; e += nthr) {
        int r = ei[e];
        int c = col[e];
        if ((unsigned)r >= (unsigned)N_NODES || (unsigned)c >= (unsigned)N_NODES)
            continue;
        int pos = atomicAdd(&g_cur[c], 1);
        float w = g_dinv[r] * g_dinv[c];
        g_edge[pos] = make_int2(r, __float_as_int(w));
    }
    gbar(5);

    // ---- 3 GCN layers ----
    for (int l = 0; l < 3; l++) {
        const float* W = (l == 0) ? W0 : (l == 1) ? W1 : W2;
        const float* B = (l == 0) ? B0 : (l == 1) ? B1 : B2;

        // stage W into smem
        const float4* W4 = (const float4*)W;
        for (int i = tid; i < DH * 16; i += 256) sh[i] = W4[i];
        __syncthreads();

        // GEMM: t16 = fp16(in @ W); 4 nodes per thread, f32x2 packed
        const float4* base = l ? g_h : (const float4*)x;
        for (int idx = gt; idx < (N_NODES / 4) * 16; idx += nthr) {
            int quad  = idx >> 4;
            int g     = idx & 15;
            int node0 = quad * 4;

            unsigned long long acc01[4] = {0, 0, 0, 0};
            unsigned long long acc23[4] = {0, 0, 0, 0};
#pragma unroll
            for (int k4 = 0; k4 < 16; k4++) {
                float4 xv[4];
#pragma unroll
                for (int i = 0; i < 4; i++) xv[i] = base[(node0 + i) * 16 + k4];
#pragma unroll
                for (int s = 0; s < 4; s++) {
                    float4 w = sh[(k4 * 4 + s) * 16 + g];
                    unsigned long long w01 = pk2(w.x, w.y);
                    unsigned long long w23 = pk2(w.z, w.w);
#pragma unroll
                    for (int i = 0; i < 4; i++) {
                        float xk = (s == 0) ? xv[i].x : (s == 1) ? xv[i].y
                                 : (s == 2) ? xv[i].z : xv[i].w;
                        unsigned long long xx = pk2(xk, xk);
                        fma2(acc01[i], w01, xx);
                        fma2(acc23[i], w23, xx);
                    }
                }
            }
#pragma unroll
            for (int i = 0; i < 4; i++) {
                float2 lo = upk2(acc01[i]);
                float2 hi = upk2(acc23[i]);
                __half2 h01 = __floats2half2_rn(lo.x, lo.y);
                __half2 h23 = __floats2half2_rn(hi.x, hi.y);
                uint2 u;
                u.x = *(const unsigned int*)&h01;
                u.y = *(const unsigned int*)&h23;
                g_t16[(node0 + i) * 16 + g] = u;
            }
        }
        gbar(6 + l * 2);

        // aggregate: h = relu(csr_sum + selfloop + bias)
        for (int idx = gt; idx < N_NODES * 16; idx += nthr) {
            int node = idx >> 4;
            int f    = idx & 15;
            int beg = g_off[node];
            int end = g_off[node + 1];
            float di = g_dinv[node];
            float s = di * di;

            float2 sa, sb;
            upk_h4(g_t16[node * 16 + f], sa, sb);
            float4 acc = make_float4(sa.x * s, sa.y * s, sb.x * s, sb.y * s);

            int j = beg;
            for (; j + 3 < end; j += 4) {
                int2 e0 = g_edge[j];
                int2 e1 = g_edge[j + 1];
                int2 e2 = g_edge[j + 2];
                int2 e3 = g_edge[j + 3];
                uint2 u0 = g_t16[e0.x * 16 + f];
                uint2 u1 = g_t16[e1.x * 16 + f];
                uint2 u2 = g_t16[e2.x * 16 + f];
                uint2 u3 = g_t16[e3.x * 16 + f];
                float2 a, b;
                float w;
                w = __int_as_float(e0.y); upk_h4(u0, a, b);
                acc.x = fmaf(w, a.x, acc.x); acc.y = fmaf(w, a.y, acc.y);
                acc.z = fmaf(w, b.x, acc.z); acc.w = fmaf(w, b.y, acc.w);
                w = __int_as_float(e1.y); upk_h4(u1, a, b);
                acc.x = fmaf(w, a.x, acc.x); acc.y = fmaf(w, a.y, acc.y);
                acc.z = fmaf(w, b.x, acc.z); acc.w = fmaf(w, b.y, acc.w);
                w = __int_as_float(e2.y); upk_h4(u2, a, b);
                acc.x = fmaf(w, a.x, acc.x); acc.y = fmaf(w, a.y, acc.y);
                acc.z = fmaf(w, b.x, acc.z); acc.w = fmaf(w, b.y, acc.w);
                w = __int_as_float(e3.y); upk_h4(u3, a, b);
                acc.x = fmaf(w, a.x, acc.x); acc.y = fmaf(w, a.y, acc.y);
                acc.z = fmaf(w, b.x, acc.z); acc.w = fmaf(w, b.y, acc.w);
            }
            for (; j < end; j++) {
                int2 e0 = g_edge[j];
                float2 a, b;
                upk_h4(g_t16[e0.x * 16 + f], a, b);
                float w = __int_as_float(e0.y);
                acc.x = fmaf(w, a.x, acc.x); acc.y = fmaf(w, a.y, acc.y);
                acc.z = fmaf(w, b.x, acc.z); acc.w = fmaf(w, b.y, acc.w);
            }

            float4 b4 = ((const float4*)B)[f];
            float4 r;
            r.x = fmaxf(acc.x + b4.x, 0.f);
            r.y = fmaxf(acc.y + b4.y, 0.f);
            r.z = fmaxf(acc.z + b4.z, 0.f);
            r.w = fmaxf(acc.w + b4.w, 0.f);
            g_h[node * 16 + f] = r;
        }
        gbar(7 + l * 2);
    }

    // ---- pool: one block per graph (blocks 0..63) ----
    if (bid < NG) {
        int f  = tid & 15;
        int r0 = tid >> 4;
        int beg = g_start[bid];
        int end = g_start[bid + 1];

        float4 acc = make_float4(0.f, 0.f, 0.f, 0.f);
        for (int r = beg + r0; r < end; r += 16) acc = f4add(acc, g_h[r * 16 + f]);
        sh[tid] = acc;
        __syncthreads();
#pragma unroll
        for (int s = 8; s > 0; s >>= 1) {
            if (r0 < s) sh[tid] = f4add(sh[tid], sh[tid + s * 16]);
            __syncthreads();
        }
        if (r0 == 0) {
            float inv = 1.0f / fmaxf((float)(end - beg), 1.0f);
            float4 v = sh[f];
            v.x *= inv; v.y *= inv; v.z *= inv; v.w *= inv;
            ((float4*)out)[bid * 16 + f] = v;
        }
    }

    // ---- end-of-run: last block resets barrier state for the next replay --
    if (tid == 0) {
        __threadfence();
        unsigned int old = atomicAdd(&g_done, 1u);
        if (old == (unsigned int)nblk - 1) {
            for (int k = 0; k < NBAR; k++) g_bar[k] = 0;
            __threadfence();
            g_done = 0;
        }
    }
}

// ---------------- launch: bind inputs BY ELEMENT COUNT --------------------
extern "C" void kernel_launch(void* const* d_in, const int* in_sizes, int n_in,
                              void* d_out, int out_size) {
    const float* x     = 0;
    const int*   ei    = 0;
    const int*   batch = 0;
    const float* W[3] = {0, 0, 0};
    const float* B[3] = {0, 0, 0};
    int nw = 0, nb = 0;

    for (int i = 0; i < n_in; i++) {
        int sz = in_sizes[i];
        if      (sz == N_NODES * DH)  x     = (const float*)d_in[i];
        else if (sz == 2 * N_EDGES)   ei    = (const int*)d_in[i];
        else if (sz == N_NODES)       batch = (const int*)d_in[i];
        else if (sz == DH * DH) { if (nw < 3) W[nw++] = (const float*)d_in[i]; }
        else if (sz == DH)      { if (nb < 3) B[nb++] = (const float*)d_in[i]; }
    }
    if (!x || !ei || !batch || nw != 3 || nb != 3) return;

    // size the persistent grid to exactly-resident capacity
    int dev = 0;
    cudaGetDevice(&dev);
    int nsm = 0;
    cudaDeviceGetAttribute(&nsm, cudaDevAttrMultiProcessorCount, dev);
    int bpm = 0;
    cudaOccupancyMaxActiveBlocksPerMultiprocessor(&bpm, fused_gcn, 256, 0);
    if (bpm < 1) bpm = 1;
    if (nsm < 1) nsm = 1;
    int grid = nsm * bpm;
    if (grid < NG) grid = NG;  // pool needs >= 64 blocks (resident anyway)

    fused_gcn<<<grid, 256>>>(x, ei, batch,
                             W[0], B[0], W[1], B[1], W[2], B[2],
                             (float*)d_out);
}

// round 10
// speedup vs baseline: 2.6053x; 2.6053x over previous
#include <cuda_runtime.h>
#include <cuda_fp16.h>

#define N_NODES 50000
#define N_EDGES 800000
#define DH 64
#define NG 64

#define SCAN_B 512
#define SCAN_NBLK ((N_NODES + SCAN_B - 1) / SCAN_B)   // 98

// ---------------- device scratch ----------------
__device__ float  g_dinv[N_NODES];
__device__ int    g_degi[N_NODES];          // zero-init static; re-zeroed by scan1
__device__ int    g_off[N_NODES + 1];
__device__ int    g_cur[N_NODES];
__device__ int    g_bsum[SCAN_NBLK];
__device__ int2   g_edge[N_EDGES];
__device__ uint2  g_t16[N_NODES * 16];      // t in fp16 (4 halfs per uint2)
__device__ float4 g_h[N_NODES * 16];        // layer output (fp32)
__device__ int    g_start[NG + 1];

__device__ __forceinline__ float4 f4add(float4 a, float4 b) {
    return make_float4(a.x + b.x, a.y + b.y, a.z + b.z, a.w + b.w);
}

// packed f32x2 helpers (Blackwell dual-FP32 pipe; PTX-only)
__device__ __forceinline__ unsigned long long pk2(float a, float b) {
    unsigned long long r;
    asm("mov.b64 %0, {%1, %2};" : "=l"(r) : "f"(a), "f"(b));
    return r;
}
__device__ __forceinline__ void fma2(unsigned long long& d,
                                     unsigned long long a, unsigned long long b) {
    asm("fma.rn.f32x2 %0, %1, %2, %0;" : "+l"(d) : "l"(a), "l"(b));
}
__device__ __forceinline__ float2 upk2(unsigned long long v) {
    float2 f;
    asm("mov.b64 {%0, %1}, %2;" : "=f"(f.x), "=f"(f.y) : "l"(v));
    return f;
}
__device__ __forceinline__ void upk_h4(uint2 u, float2& a, float2& b) {
    a = __half22float2(*(const __half2*)&u.x);
    b = __half22float2(*(const __half2*)&u.y);
}

// ---------------- prep ----------------
__global__ void deg_kernel(const int* __restrict__ col) {
    int e = blockIdx.x * blockDim.x + threadIdx.x;
    if (e < N_EDGES) {
        int c = col[e];
        if ((unsigned)c < (unsigned)N_NODES) atomicAdd(&g_degi[c], 1);
    }
}

// per-block scan of degrees; fused dinv; re-zeroes degi for next run
__global__ void scan1_kernel() {
    __shared__ int s[SCAN_B];
    int t = threadIdx.x;
    int i = blockIdx.x * SCAN_B + t;
    int v = (i < N_NODES) ? g_degi[i] : 0;
    if (i < N_NODES) {
        g_dinv[i] = rsqrtf((float)v + 1.0f);   // +1 self loop
        g_degi[i] = 0;                         // clear for next launch/run
    }
    s[t] = v;
    __syncthreads();
#pragma unroll
    for (int d = 1; d < SCAN_B; d <<= 1) {
        int u = (t >= d) ? s[t - d] : 0;
        __syncthreads();
        s[t] += u;
        __syncthreads();
    }
    if (i < N_NODES) g_off[i] = s[t] - v;
    if (t == SCAN_B - 1) g_bsum[blockIdx.x] = s[t];
}

// phase 2+3 fused (+ graph bounds): every block redundantly scans the 98
// block sums in smem, then adds the prefix to its slice.
__global__ void scan3_kernel(const int* __restrict__ batch) {
    __shared__ int s[128];
    int t = threadIdx.x;  // 256 threads
    if (t < 128) {
        int v = (t < SCAN_NBLK) ? g_bsum[t] : 0;
        s[t] = v;
    }
    __syncthreads();
#pragma unroll
    for (int d = 1; d < 128; d <<= 1) {
        int u = 0;
        if (t < 128 && t >= d) u = s[t - d];
        __syncthreads();
        if (t < 128) s[t] += u;
        __syncthreads();
    }
    int i = blockIdx.x * blockDim.x + t;
    if (i < N_NODES) {
        int blk = i / SCAN_B;
        int pre = s[blk] - g_bsum[blk];
        int off = g_off[i] + pre;
        g_off[i] = off;
        g_cur[i] = off;
        if (i == 0) g_off[N_NODES] = s[127];

        int b  = batch[i];
        int bp = (i == 0) ? -1 : batch[i - 1];
        if (b < 0) b = 0;
        if (b >= NG) b = NG - 1;
        if (bp < -1) bp = -1;
        if (bp >= NG) bp = NG - 1;
        for (int g = bp + 1; g <= b; g++) g_start[g] = i;
        if (i == N_NODES - 1)
            for (int g = b + 1; g <= NG; g++) g_start[g] = N_NODES;
    }
}

__global__ void scatter_kernel(const int* __restrict__ ei) {
    int e = blockIdx.x * blockDim.x + threadIdx.x;
    if (e >= N_EDGES) return;
    int r = ei[e];
    int c = ei[N_EDGES + e];
    if ((unsigned)r >= (unsigned)N_NODES || (unsigned)c >= (unsigned)N_NODES)
        return;
    int pos = atomicAdd(&g_cur[c], 1);
    float w = g_dinv[r] * g_dinv[c];
    g_edge[pos] = make_int2(r, __float_as_int(w));
}

// ---------------- GEMM: t16 = fp16(in @ W) ; 4 nodes/thread, f32x2 --------
#define GEMM_B 256
__global__ void gemm_kernel(const float* __restrict__ in,
                            const float* __restrict__ W, int use_h) {
    __shared__ float4 Ws[DH * 16];  // 16 KB
    const float4* W4 = (const float4*)W;
    for (int i = threadIdx.x; i < DH * 16; i += GEMM_B) Ws[i] = W4[i];
    __syncthreads();

    int tid  = blockIdx.x * GEMM_B + threadIdx.x;
    int quad = tid >> 4;
    int g    = tid & 15;
    int node0 = quad * 4;
    if (node0 >= N_NODES) return;

    const float4* base = use_h ? g_h : (const float4*)in;

    unsigned long long acc01[4] = {0, 0, 0, 0};
    unsigned long long acc23[4] = {0, 0, 0, 0};

#pragma unroll
    for (int k4 = 0; k4 < 16; k4++) {
        float4 xv[4];
#pragma unroll
        for (int i = 0; i < 4; i++) xv[i] = base[(node0 + i) * 16 + k4];
#pragma unroll
        for (int s = 0; s < 4; s++) {
            float4 w = Ws[(k4 * 4 + s) * 16 + g];
            unsigned long long w01 = pk2(w.x, w.y);
            unsigned long long w23 = pk2(w.z, w.w);
#pragma unroll
            for (int i = 0; i < 4; i++) {
                float xk = (s == 0) ? xv[i].x : (s == 1) ? xv[i].y
                         : (s == 2) ? xv[i].z : xv[i].w;
                unsigned long long xx = pk2(xk, xk);
                fma2(acc01[i], w01, xx);
                fma2(acc23[i], w23, xx);
            }
        }
    }
#pragma unroll
    for (int i = 0; i < 4; i++) {
        float2 lo = upk2(acc01[i]);
        float2 hi = upk2(acc23[i]);
        __half2 h01 = __floats2half2_rn(lo.x, lo.y);
        __half2 h23 = __floats2half2_rn(hi.x, hi.y);
        uint2 u;
        u.x = *(const unsigned int*)&h01;
        u.y = *(const unsigned int*)&h23;
        g_t16[(node0 + i) * 16 + g] = u;
    }
}

// ---------------- fused aggregate: h = relu(csr_sum + selfloop + bias) ----
__global__ void agg_kernel(const float* __restrict__ bias) {
    int tid  = blockIdx.x * blockDim.x + threadIdx.x;
    int node = tid >> 4;
    int f    = tid & 15;
    if (node >= N_NODES) return;

    int beg = g_off[node];
    int end = g_off[node + 1];
    float di = g_dinv[node];
    float s = di * di;

    float2 sa, sb;
    upk_h4(g_t16[node * 16 + f], sa, sb);
    float4 acc = make_float4(sa.x * s, sa.y * s, sb.x * s, sb.y * s);

    int j = beg;
    for (; j + 7 < end; j += 8) {   // 8-deep for MLP
        int2  ee[8];
        uint2 uu[8];
#pragma unroll
        for (int q = 0; q < 8; q++) ee[q] = g_edge[j + q];
#pragma unroll
        for (int q = 0; q < 8; q++) uu[q] = g_t16[ee[q].x * 16 + f];
#pragma unroll
        for (int q = 0; q < 8; q++) {
            float2 a, b;
            upk_h4(uu[q], a, b);
            float w = __int_as_float(ee[q].y);
            acc.x = fmaf(w, a.x, acc.x); acc.y = fmaf(w, a.y, acc.y);
            acc.z = fmaf(w, b.x, acc.z); acc.w = fmaf(w, b.y, acc.w);
        }
    }
    for (; j < end; j++) {
        int2 e0 = g_edge[j];
        float2 a, b;
        upk_h4(g_t16[e0.x * 16 + f], a, b);
        float w = __int_as_float(e0.y);
        acc.x = fmaf(w, a.x, acc.x); acc.y = fmaf(w, a.y, acc.y);
        acc.z = fmaf(w, b.x, acc.z); acc.w = fmaf(w, b.y, acc.w);
    }

    float4 b4 = ((const float4*)bias)[f];
    float4 r;
    r.x = fmaxf(acc.x + b4.x, 0.f);
    r.y = fmaxf(acc.y + b4.y, 0.f);
    r.z = fmaxf(acc.z + b4.z, 0.f);
    r.w = fmaxf(acc.w + b4.w, 0.f);
    g_h[node * 16 + f] = r;
}

// ---------------- pooling ----------------
__global__ void pool_kernel(float* __restrict__ out) {
    __shared__ float4 sm[256];
    int g  = blockIdx.x;
    int t  = threadIdx.x;
    int f  = t & 15;
    int r0 = t >> 4;
    int beg = g_start[g];
    int end = g_start[g + 1];

    float4 acc = make_float4(0.f, 0.f, 0.f, 0.f);
    for (int r = beg + r0; r < end; r += 16) acc = f4add(acc, g_h[r * 16 + f]);
    sm[t] = acc;
    __syncthreads();
#pragma unroll
    for (int s = 8; s > 0; s >>= 1) {
        if (r0 < s) sm[t] = f4add(sm[t], sm[t + s * 16]);
        __syncthreads();
    }
    if (r0 == 0) {
        float inv = 1.0f / fmaxf((float)(end - beg), 1.0f);
        float4 v = sm[f];
        v.x *= inv; v.y *= inv; v.z *= inv; v.w *= inv;
        ((float4*)out)[g * 16 + f] = v;
    }
}

// ---------------- launch: bind inputs BY ELEMENT COUNT --------------------
extern "C" void kernel_launch(void* const* d_in, const int* in_sizes, int n_in,
                              void* d_out, int out_size) {
    const float* x     = 0;
    const int*   ei    = 0;
    const int*   batch = 0;
    const float* W[3] = {0, 0, 0};
    const float* B[3] = {0, 0, 0};
    int nw = 0, nb = 0;

    for (int i = 0; i < n_in; i++) {
        int sz = in_sizes[i];
        if      (sz == N_NODES * DH)  x     = (const float*)d_in[i];
        else if (sz == 2 * N_EDGES)   ei    = (const int*)d_in[i];
        else if (sz == N_NODES)       batch = (const int*)d_in[i];
        else if (sz == DH * DH) { if (nw < 3) W[nw++] = (const float*)d_in[i]; }
        else if (sz == DH)      { if (nb < 3) B[nb++] = (const float*)d_in[i]; }
    }
    if (!x || !ei || !batch || nw != 3 || nb != 3) return;

    float* out = (float*)d_out;

    const int TB = 256;
    const int gE    = (N_EDGES + TB - 1) / TB;        // 3125
    const int gN    = (N_NODES + TB - 1) / TB;        // 196
    const int gN16  = (N_NODES * 16 + TB - 1) / TB;   // 3125
    const int gQ    = (N_NODES / 4 * 16 + GEMM_B - 1) / GEMM_B;  // 782

    // ---- CSR build + norms (once per run; degi pre-zeroed by prior scan1) --
    deg_kernel<<<gE, TB>>>(ei + N_EDGES);
    scan1_kernel<<<SCAN_NBLK, SCAN_B>>>();
    scan3_kernel<<<gN, TB>>>(batch);
    scatter_kernel<<<gE, TB>>>(ei);

    // ---- 3 GCN layers ----
    for (int l = 0; l < 3; l++) {
        gemm_kernel<<<gQ, GEMM_B>>>(x, W[l], l > 0);
        agg_kernel<<<gN16, TB>>>(B[l]);
    }

    // ---- global mean pool ----
    pool_kernel<<<NG, 256>>>(out);
}

// round 11
// speedup vs baseline: 2.6641x; 1.0226x over previous
#include <cuda_runtime.h>
#include <cuda_fp16.h>

#define N_NODES 50000
#define N_EDGES 800000
#define DH 64
#define NG 64

#define SCAN_B 512
#define SCAN_NBLK ((N_NODES + SCAN_B - 1) / SCAN_B)   // 98

// ---------------- device scratch ----------------
__device__ float  g_dinv[N_NODES];
__device__ int    g_degi[N_NODES];          // zero-init static; re-zeroed by scan1
__device__ int    g_off[N_NODES + 1];
__device__ int    g_cur[N_NODES];
__device__ int    g_bsum[SCAN_NBLK];
__device__ int    g_edge[N_EDGES];          // src index only (w recomputed in agg)
__device__ uint2  g_t16[N_NODES * 16];      // t  in fp16 (4 halfs per uint2)
__device__ uint2  g_h16[N_NODES * 16];      // h  in fp16
__device__ int    g_start[NG + 1];

// packed f32x2 helpers (Blackwell dual-FP32 pipe; PTX-only)
__device__ __forceinline__ unsigned long long pk2(float a, float b) {
    unsigned long long r;
    asm("mov.b64 %0, {%1, %2};" : "=l"(r) : "f"(a), "f"(b));
    return r;
}
__device__ __forceinline__ void fma2(unsigned long long& d,
                                     unsigned long long a, unsigned long long b) {
    asm("fma.rn.f32x2 %0, %1, %2, %0;" : "+l"(d) : "l"(a), "l"(b));
}
__device__ __forceinline__ float2 upk2(unsigned long long v) {
    float2 f;
    asm("mov.b64 {%0, %1}, %2;" : "=f"(f.x), "=f"(f.y) : "l"(v));
    return f;
}
__device__ __forceinline__ void upk_h4(uint2 u, float2& a, float2& b) {
    a = __half22float2(*(const __half2*)&u.x);
    b = __half22float2(*(const __half2*)&u.y);
}
__device__ __forceinline__ uint2 pk_h4(float x, float y, float z, float w) {
    __half2 h01 = __floats2half2_rn(x, y);
    __half2 h23 = __floats2half2_rn(z, w);
    uint2 u;
    u.x = *(const unsigned int*)&h01;
    u.y = *(const unsigned int*)&h23;
    return u;
}

// ---------------- prep ----------------
__global__ void deg_kernel(const int* __restrict__ col) {
    int e = blockIdx.x * blockDim.x + threadIdx.x;
    if (e < N_EDGES) {
        int c = col[e];
        if ((unsigned)c < (unsigned)N_NODES) atomicAdd(&g_degi[c], 1);
    }
}

// per-block scan of degrees; fused dinv; re-zeroes degi for next run
__global__ void scan1_kernel() {
    __shared__ int s[SCAN_B];
    int t = threadIdx.x;
    int i = blockIdx.x * SCAN_B + t;
    int v = (i < N_NODES) ? g_degi[i] : 0;
    if (i < N_NODES) {
        g_dinv[i] = rsqrtf((float)v + 1.0f);   // +1 self loop
        g_degi[i] = 0;                         // clear for next run
    }
    s[t] = v;
    __syncthreads();
#pragma unroll
    for (int d = 1; d < SCAN_B; d <<= 1) {
        int u = (t >= d) ? s[t - d] : 0;
        __syncthreads();
        s[t] += u;
        __syncthreads();
    }
    if (i < N_NODES) g_off[i] = s[t] - v;
    if (t == SCAN_B - 1) g_bsum[blockIdx.x] = s[t];
}

// phase 2+3 fused (+ graph bounds)
__global__ void scan3_kernel(const int* __restrict__ batch) {
    __shared__ int s[128];
    int t = threadIdx.x;  // 256 threads
    if (t < 128) {
        int v = (t < SCAN_NBLK) ? g_bsum[t] : 0;
        s[t] = v;
    }
    __syncthreads();
#pragma unroll
    for (int d = 1; d < 128; d <<= 1) {
        int u = 0;
        if (t < 128 && t >= d) u = s[t - d];
        __syncthreads();
        if (t < 128) s[t] += u;
        __syncthreads();
    }
    int i = blockIdx.x * blockDim.x + t;
    if (i < N_NODES) {
        int blk = i / SCAN_B;
        int pre = s[blk] - g_bsum[blk];
        int off = g_off[i] + pre;
        g_off[i] = off;
        g_cur[i] = off;
        if (i == 0) g_off[N_NODES] = s[127];

        int b  = batch[i];
        int bp = (i == 0) ? -1 : batch[i - 1];
        if (b < 0) b = 0;
        if (b >= NG) b = NG - 1;
        if (bp < -1) bp = -1;
        if (bp >= NG) bp = NG - 1;
        for (int g = bp + 1; g <= b; g++) g_start[g] = i;
        if (i == N_NODES - 1)
            for (int g = b + 1; g <= NG; g++) g_start[g] = N_NODES;
    }
}

__global__ void scatter_kernel(const int* __restrict__ ei) {
    int e = blockIdx.x * blockDim.x + threadIdx.x;
    if (e >= N_EDGES) return;
    int r = ei[e];
    int c = ei[N_EDGES + e];
    if ((unsigned)r >= (unsigned)N_NODES || (unsigned)c >= (unsigned)N_NODES)
        return;
    int pos = atomicAdd(&g_cur[c], 1);
    g_edge[pos] = r;                           // 4B random write (w derived later)
}

// ---------------- GEMM: t16 = fp16(in @ W) ; 4 nodes/thread, f32x2 --------
#define GEMM_B 256
template <bool USEH>
__global__ void gemm_kernel(const float* __restrict__ in,
                            const float* __restrict__ W) {
    __shared__ float4 Ws[DH * 16];  // 16 KB
    const float4* W4 = (const float4*)W;
    for (int i = threadIdx.x; i < DH * 16; i += GEMM_B) Ws[i] = W4[i];
    __syncthreads();

    int tid  = blockIdx.x * GEMM_B + threadIdx.x;
    int quad = tid >> 4;
    int g    = tid & 15;
    int node0 = quad * 4;
    if (node0 >= N_NODES) return;

    unsigned long long acc01[4] = {0, 0, 0, 0};
    unsigned long long acc23[4] = {0, 0, 0, 0};

#pragma unroll
    for (int k4 = 0; k4 < 16; k4++) {
        float4 xv[4];
#pragma unroll
        for (int i = 0; i < 4; i++) {
            if (USEH) {
                float2 a, b;
                upk_h4(g_h16[(node0 + i) * 16 + k4], a, b);
                xv[i] = make_float4(a.x, a.y, b.x, b.y);
            } else {
                xv[i] = ((const float4*)in)[(node0 + i) * 16 + k4];
            }
        }
#pragma unroll
        for (int s = 0; s < 4; s++) {
            float4 w = Ws[(k4 * 4 + s) * 16 + g];
            unsigned long long w01 = pk2(w.x, w.y);
            unsigned long long w23 = pk2(w.z, w.w);
#pragma unroll
            for (int i = 0; i < 4; i++) {
                float xk = (s == 0) ? xv[i].x : (s == 1) ? xv[i].y
                         : (s == 2) ? xv[i].z : xv[i].w;
                unsigned long long xx = pk2(xk, xk);
                fma2(acc01[i], w01, xx);
                fma2(acc23[i], w23, xx);
            }
        }
    }
#pragma unroll
    for (int i = 0; i < 4; i++) {
        float2 lo = upk2(acc01[i]);
        float2 hi = upk2(acc23[i]);
        g_t16[(node0 + i) * 16 + g] = pk_h4(lo.x, lo.y, hi.x, hi.y);
    }
}

// ---------------- fused aggregate: h16 = relu(csr_sum + selfloop + bias) --
__global__ void agg_kernel(const float* __restrict__ bias) {
    int tid  = blockIdx.x * blockDim.x + threadIdx.x;
    int node = tid >> 4;
    int f    = tid & 15;
    if (node >= N_NODES) return;

    int beg = g_off[node];
    int end = g_off[node + 1];
    float di = g_dinv[node];

    float2 sa, sb;
    upk_h4(g_t16[node * 16 + f], sa, sb);
    float s = di * di;
    float4 acc = make_float4(sa.x * s, sa.y * s, sb.x * s, sb.y * s);

    int j = beg;
    for (; j + 7 < end; j += 8) {   // 8-deep for MLP
        int   ee[8];
        float dd[8];
        uint2 uu[8];
#pragma unroll
        for (int q = 0; q < 8; q++) ee[q] = g_edge[j + q];
#pragma unroll
        for (int q = 0; q < 8; q++) dd[q] = g_dinv[ee[q]];
#pragma unroll
        for (int q = 0; q < 8; q++) uu[q] = g_t16[ee[q] * 16 + f];
#pragma unroll
        for (int q = 0; q < 8; q++) {
            float2 a, b;
            upk_h4(uu[q], a, b);
            float w = di * dd[q];
            acc.x = fmaf(w, a.x, acc.x); acc.y = fmaf(w, a.y, acc.y);
            acc.z = fmaf(w, b.x, acc.z); acc.w = fmaf(w, b.y, acc.w);
        }
    }
    for (; j < end; j++) {
        int src = g_edge[j];
        float2 a, b;
        upk_h4(g_t16[src * 16 + f], a, b);
        float w = di * g_dinv[src];
        acc.x = fmaf(w, a.x, acc.x); acc.y = fmaf(w, a.y, acc.y);
        acc.z = fmaf(w, b.x, acc.z); acc.w = fmaf(w, b.y, acc.w);
    }

    float4 b4 = ((const float4*)bias)[f];
    g_h16[node * 16 + f] = pk_h4(fmaxf(acc.x + b4.x, 0.f),
                                 fmaxf(acc.y + b4.y, 0.f),
                                 fmaxf(acc.z + b4.z, 0.f),
                                 fmaxf(acc.w + b4.w, 0.f));
}

// ---------------- pooling (fp32 accumulation over fp16 h) -----------------
__global__ void pool_kernel(float* __restrict__ out) {
    __shared__ float4 sm[256];
    int g  = blockIdx.x;
    int t  = threadIdx.x;
    int f  = t & 15;
    int r0 = t >> 4;
    int beg = g_start[g];
    int end = g_start[g + 1];

    float4 acc = make_float4(0.f, 0.f, 0.f, 0.f);
    for (int r = beg + r0; r < end; r += 16) {
        float2 a, b;
        upk_h4(g_h16[r * 16 + f], a, b);
        acc.x += a.x; acc.y += a.y; acc.z += b.x; acc.w += b.y;
    }
    sm[t] = acc;
    __syncthreads();
#pragma unroll
    for (int s = 8; s > 0; s >>= 1) {
        if (r0 < s) {
            float4 o = sm[t + s * 16];
            float4 m = sm[t];
            sm[t] = make_float4(m.x + o.x, m.y + o.y, m.z + o.z, m.w + o.w);
        }
        __syncthreads();
    }
    if (r0 == 0) {
        float inv = 1.0f / fmaxf((float)(end - beg), 1.0f);
        float4 v = sm[f];
        v.x *= inv; v.y *= inv; v.z *= inv; v.w *= inv;
        ((float4*)out)[g * 16 + f] = v;
    }
}

// ---------------- launch: bind inputs BY ELEMENT COUNT --------------------
extern "C" void kernel_launch(void* const* d_in, const int* in_sizes, int n_in,
                              void* d_out, int out_size) {
    const float* x     = 0;
    const int*   ei    = 0;
    const int*   batch = 0;
    const float* W[3] = {0, 0, 0};
    const float* B[3] = {0, 0, 0};
    int nw = 0, nb = 0;

    for (int i = 0; i < n_in; i++) {
        int sz = in_sizes[i];
        if      (sz == N_NODES * DH)  x     = (const float*)d_in[i];
        else if (sz == 2 * N_EDGES)   ei    = (const int*)d_in[i];
        else if (sz == N_NODES)       batch = (const int*)d_in[i];
        else if (sz == DH * DH) { if (nw < 3) W[nw++] = (const float*)d_in[i]; }
        else if (sz == DH)      { if (nb < 3) B[nb++] = (const float*)d_in[i]; }
    }
    if (!x || !ei || !batch || nw != 3 || nb != 3) return;

    float* out = (float*)d_out;

    const int TB = 256;
    const int gE    = (N_EDGES + TB - 1) / TB;        // 3125
    const int gN    = (N_NODES + TB - 1) / TB;        // 196
    const int gN16  = (N_NODES * 16 + TB - 1) / TB;   // 3125
    const int gQ    = (N_NODES / 4 * 16 + GEMM_B - 1) / GEMM_B;  // 782

    // ---- CSR build + norms ----
    deg_kernel<<<gE, TB>>>(ei + N_EDGES);
    scan1_kernel<<<SCAN_NBLK, SCAN_B>>>();
    scan3_kernel<<<gN, TB>>>(batch);
    scatter_kernel<<<gE, TB>>>(ei);

    // ---- 3 GCN layers ----
    gemm_kernel<false><<<gQ, GEMM_B>>>(x, W[0]);
    agg_kernel<<<gN16, TB>>>(B[0]);
    gemm_kernel<true><<<gQ, GEMM_B>>>(x, W[1]);
    agg_kernel<<<gN16, TB>>>(B[1]);
    gemm_kernel<true><<<gQ, GEMM_B>>>(x, W[2]);
    agg_kernel<<<gN16, TB>>>(B[2]);

    // ---- global mean pool ----
    pool_kernel<<<NG, 256>>>(out);
}